// round 4
// baseline (speedup 1.0000x reference)
#include <cuda_runtime.h>
#include <math.h>

#define NB 8
#define NGT 100
#define NC 80
#define T_TOTAL 13343

// One block per (batch, gt-box); 5 warps, warp l owns FPN level l.
// Semantics (validated against R3 rel_err): plain masked argmin —
//   loss_l = (sum_masked cls_loc)/cnt + (sum_masked iou_loc)/cnt
// (unmasked cells contribute nothing; XLA lowers x*bool to select).
// Masked-cell NaN still propagates; final argmin = numpy: first NaN wins,
// else first strict min. Output dtype float32; invalid box -> -1.0f.
__global__ void level_select_kernel(const float* __restrict__ cls,
                                    const float* __restrict__ regr,
                                    const float* __restrict__ gt,
                                    float* __restrict__ out) {
    const int   fdim_[5] = {100, 50, 25, 13, 7};
    const int   ls_[5]   = {0, 10000, 12500, 13125, 13294};
    const float st_[5]   = {8.f, 16.f, 32.f, 64.f, 128.f};

    int bn  = blockIdx.x;                 // b*100 + n
    int b   = bn / NGT;
    int tid = threadIdx.x;
    int l   = tid >> 5;                   // warp id = level
    int lane = tid & 31;

    __shared__ float  sbox[5];
    __shared__ double lvl[5];

    if (tid < 5) sbox[tid] = gt[(size_t)bn * 5 + tid];
    __syncthreads();

    float b0 = sbox[0], b1 = sbox[1], b2 = sbox[2], b3 = sbox[3];
    int   label = (int)sbox[4];
    if (!((fabsf(b0) + fabsf(b1) + fabsf(b2) + fabsf(b3)) > 0.0f)) {
        if (tid == 0) out[bn] = -1.0f;
        return;
    }

    const float* clsb = cls  + (size_t)b * T_TOTAL * NC;
    const float* regb = regr + (size_t)b * T_TOTAL * 4;

    {
        float stride = st_[l];
        int   fw = fdim_[l], fh = fdim_[l], ls = ls_[l];

        // center-sampling rectangle: exact f32 replica of the reference
        float pb0 = b0 / stride, pb1 = b1 / stride;
        float pb2 = b2 / stride, pb3 = b3 / stride;
        float cx = (pb0 + pb2) * 0.5f, cy = (pb1 + pb3) * 0.5f;
        float hw = ((pb2 - pb0) * 0.2f) * 0.5f;
        float hh = ((pb3 - pb1) * 0.2f) * 0.5f;
        int x1 = (int)fminf(fmaxf(floorf(cx - hw), 0.0f), (float)(fw - 1));
        int y1 = (int)fminf(fmaxf(floorf(cy - hh), 0.0f), (float)(fh - 1));
        int x2 = min(max((int)ceilf(cx + hw), x1 + 1), fw);
        int y2 = min(max((int)ceilf(cy + hh), y1 + 1), fh);
        int nx = x2 - x1;
        int cnt = nx * (y2 - y1);

        double s = 0.0;

        // classification part: distribute (cell, class) pairs over lanes.
        // cls_loc = s_neg - neg_lab + pos_lab; the label class contributes
        // (neg term) - neg_lab + pos_lab, folded per-term here.
        int total = cnt * NC;
        for (int j = lane; j < total; j += 32) {
            int cell = j / NC;
            int c    = j - cell * NC;
            int x = x1 + cell % nx;
            int y = y1 + cell / nx;
            int t = ls + y * fw + x;
            float cp = fminf(fmaxf(clsb[(size_t)t * NC + c], 1e-6f),
                             1.0f - 1e-6f);
            float neg = (0.75f * (cp * cp)) * (-logf(1.0f - cp));
            s += (double)neg;
            if (c == label) {
                float om = 1.0f - cp;
                float pos = (0.25f * (om * om)) * (-logf(cp));
                s += (double)pos - (double)neg;   // cancel label's neg term
            }
        }

        // regression (IoU) part: lanes over cells
        for (int cell = lane; cell < cnt; cell += 32) {
            int x = x1 + cell % nx;
            int y = y1 + cell / nx;
            int t = ls + y * fw + x;
            const float* rp = regb + (size_t)t * 4;
            float pl = rp[0], pt = rp[1], pr = rp[2], pbm = rp[3];
            float sx = ((float)x + 0.5f) * stride;
            float sy = ((float)y + 0.5f) * stride;
            float tl = (sx - b0) * 0.25f, tt = (sy - b1) * 0.25f;
            float tr = (b2 - sx) * 0.25f, tb = (b3 - sy) * 0.25f;
            float t_area = (tl + tr) * (tt + tb);
            float p_area = (pl + pr) * (pt + pbm);
            float wi = fminf(pl, tl) + fminf(pr, tr);
            float hi = fminf(pt, tt) + fminf(pbm, tb);
            float ai = wi * hi;
            float un = t_area + p_area - ai;
            float val = -logf((ai + 1.0f) / (un + 1.0f));  // NaN/inf propagate
            s += (double)val;
        }

        // warp reduction (doubles shuffle as 64-bit)
        #pragma unroll
        for (int o = 16; o; o >>= 1) s += __shfl_down_sync(0xffffffffu, s, o);
        if (lane == 0) lvl[l] = s / (double)cnt;
    }
    __syncthreads();

    if (tid == 0) {
        // numpy/jax argmin fold: pick op if op<acc, or op is NaN and acc isn't;
        // ties keep the earlier index.
        int    best = 0;
        double bv   = lvl[0];
        #pragma unroll
        for (int k = 1; k < 5; k++) {
            double v = lvl[k];
            bool pick = (v < bv) || ((v != v) && (bv == bv));
            if (pick) { bv = v; best = k; }
        }
        out[bn] = (float)best;
    }
}

extern "C" void kernel_launch(void* const* d_in, const int* in_sizes, int n_in,
                              void* d_out, int out_size) {
    const float* cls  = (const float*)d_in[0];  // (8, 13343, 80) f32
    const float* regr = (const float*)d_in[1];  // (8, 13343, 4)  f32
    // d_in[2] = feature_shapes (compile-time constants, unused)
    const float* gt   = (const float*)d_in[3];  // (8, 100, 5)    f32
    float* out = (float*)d_out;                 // (8, 100)       f32

    level_select_kernel<<<NB * NGT, 160>>>(cls, regr, gt, out);
}

// round 5
// speedup vs baseline: 1.8466x; 1.8466x over previous
#include <cuda_runtime.h>
#include <math.h>

#define NB 8
#define NGT 100
#define NC 80
#define T_TOTAL 13343
#define NT 256          // threads per block

// One block per (batch, gt-box); all 8 warps cooperate on each FPN level in
// turn (balanced), 4-way unrolled loads for MLP, dual f64 accumulators.
// Semantics identical to the R4 passing kernel: masked sums / cnt per level,
// numpy-argmin fold (first NaN wins, ties -> earlier level).
__global__ __launch_bounds__(NT) void level_select_kernel(
        const float* __restrict__ cls,
        const float* __restrict__ regr,
        const float* __restrict__ gt,
        float* __restrict__ out) {
    const int   fdim_[5] = {100, 50, 25, 13, 7};
    const int   ls_[5]   = {0, 10000, 12500, 13125, 13294};
    const float st_[5]   = {8.f, 16.f, 32.f, 64.f, 128.f};

    int bn   = blockIdx.x;                // b*100 + n
    int b    = bn / NGT;
    int tid  = threadIdx.x;
    int lane = tid & 31;
    int wid  = tid >> 5;

    __shared__ float  sbox[5];
    __shared__ double wsum[NT / 32];
    __shared__ double lvl[5];

    if (tid < 5) sbox[tid] = gt[(size_t)bn * 5 + tid];
    __syncthreads();

    float b0 = sbox[0], b1 = sbox[1], b2 = sbox[2], b3 = sbox[3];
    int   label = (int)sbox[4];
    if (!((fabsf(b0) + fabsf(b1) + fabsf(b2) + fabsf(b3)) > 0.0f)) {
        if (tid == 0) out[bn] = -1.0f;
        return;
    }

    const float* clsb = cls  + (size_t)b * T_TOTAL * NC;
    const float* regb = regr + (size_t)b * T_TOTAL * 4;

    #pragma unroll
    for (int l = 0; l < 5; l++) {
        float stride = st_[l];
        int   fw = fdim_[l], ls = ls_[l];

        // center-sampling rectangle: exact f32 replica of the reference
        float pb0 = b0 / stride, pb1 = b1 / stride;
        float pb2 = b2 / stride, pb3 = b3 / stride;
        float cx = (pb0 + pb2) * 0.5f, cy = (pb1 + pb3) * 0.5f;
        float hw = ((pb2 - pb0) * 0.2f) * 0.5f;
        float hh = ((pb3 - pb1) * 0.2f) * 0.5f;
        int x1 = (int)fminf(fmaxf(floorf(cx - hw), 0.0f), (float)(fw - 1));
        int y1 = (int)fminf(fmaxf(floorf(cy - hh), 0.0f), (float)(fw - 1));
        int x2 = min(max((int)ceilf(cx + hw), x1 + 1), fw);
        int y2 = min(max((int)ceilf(cy + hh), y1 + 1), fw);
        int nx  = x2 - x1;
        int cnt = nx * (y2 - y1);

        double s0 = 0.0, s1 = 0.0;

        // ---- classification: (cell, class) pairs, 4-way unrolled ----
        int total = cnt * NC;
        int j = tid;
        for (; j + 3 * NT < total; j += 4 * NT) {
            float cpv[4];
            int   cidx[4];
            #pragma unroll
            for (int u = 0; u < 4; u++) {
                int jj   = j + u * NT;
                int cell = jj / NC;
                int c    = jj - cell * NC;
                int x = x1 + cell % nx;
                int y = y1 + cell / nx;
                int t = ls + y * fw + x;
                cidx[u] = c;
                cpv[u]  = clsb[(size_t)t * NC + c];   // independent loads
            }
            #pragma unroll
            for (int u = 0; u < 4; u++) {
                float cp  = fminf(fmaxf(cpv[u], 1e-6f), 1.0f - 1e-6f);
                float neg = (0.75f * (cp * cp)) * (-logf(1.0f - cp));
                double term = (double)neg;
                if (cidx[u] == label) {
                    float om  = 1.0f - cp;
                    float pos = (0.25f * (om * om)) * (-logf(cp));
                    term = (double)pos;               // replaces neg for label
                }
                if (u & 1) s1 += term; else s0 += term;
            }
        }
        for (; j < total; j += NT) {
            int cell = j / NC;
            int c    = j - cell * NC;
            int x = x1 + cell % nx;
            int y = y1 + cell / nx;
            int t = ls + y * fw + x;
            float cp  = fminf(fmaxf(clsb[(size_t)t * NC + c], 1e-6f),
                              1.0f - 1e-6f);
            float neg = (0.75f * (cp * cp)) * (-logf(1.0f - cp));
            if (c == label) {
                float om  = 1.0f - cp;
                s0 += (double)((0.25f * (om * om)) * (-logf(cp)));
            } else {
                s0 += (double)neg;
            }
        }

        // ---- regression (IoU): cells only (<=~81) ----
        for (int cell = tid; cell < cnt; cell += NT) {
            int x = x1 + cell % nx;
            int y = y1 + cell / nx;
            int t = ls + y * fw + x;
            const float* rp = regb + (size_t)t * 4;
            float pl = rp[0], pt = rp[1], pr = rp[2], pbm = rp[3];
            float sx = ((float)x + 0.5f) * stride;
            float sy = ((float)y + 0.5f) * stride;
            float tl = (sx - b0) * 0.25f, tt = (sy - b1) * 0.25f;
            float tr = (b2 - sx) * 0.25f, tb = (b3 - sy) * 0.25f;
            float t_area = (tl + tr) * (tt + tb);
            float p_area = (pl + pr) * (pt + pbm);
            float wi = fminf(pl, tl) + fminf(pr, tr);
            float hi = fminf(pt, tt) + fminf(pbm, tb);
            float ai = wi * hi;
            float un = t_area + p_area - ai;
            s1 += (double)(-logf((ai + 1.0f) / (un + 1.0f))); // NaN propagates
        }

        // ---- block reduction ----
        double s = s0 + s1;
        #pragma unroll
        for (int o = 16; o; o >>= 1) s += __shfl_down_sync(0xffffffffu, s, o);
        if (lane == 0) wsum[wid] = s;
        __syncthreads();
        if (tid == 0) {
            double acc = 0.0;
            #pragma unroll
            for (int w = 0; w < NT / 32; w++) acc += wsum[w];
            lvl[l] = acc / (double)cnt;
        }
        __syncthreads();
    }

    if (tid == 0) {
        // numpy/jax argmin fold: pick if v<best, or v NaN and best not.
        int    best = 0;
        double bv   = lvl[0];
        #pragma unroll
        for (int k = 1; k < 5; k++) {
            double v = lvl[k];
            if ((v < bv) || ((v != v) && (bv == bv))) { bv = v; best = k; }
        }
        out[bn] = (float)best;
    }
}

extern "C" void kernel_launch(void* const* d_in, const int* in_sizes, int n_in,
                              void* d_out, int out_size) {
    const float* cls  = (const float*)d_in[0];  // (8, 13343, 80) f32
    const float* regr = (const float*)d_in[1];  // (8, 13343, 4)  f32
    // d_in[2] = feature_shapes (compile-time constants, unused)
    const float* gt   = (const float*)d_in[3];  // (8, 100, 5)    f32
    float* out = (float*)d_out;                 // (8, 100)       f32

    level_select_kernel<<<NB * NGT, NT>>>(cls, regr, gt, out);
}